// round 15
// baseline (speedup 1.0000x reference)
#include <cuda_runtime.h>

#define N_NODES 10000
#define N_EDGES 160000
#define D1 128
#define D2 256
#define D3 512

#define GRID 148
#define TPB  1024
#define GT   (GRID * TPB)        // 151552
#define ROWSTRIDE (GT / 128)     // 1184 rows per sweep in phase P4

// ---- persistent scratch (zero at load; re-zeroed at tail of every run) ----
// pair1[n] = (g1[n], s[n]) ; pair2[n] = (a2[n], t[n])
__device__ __align__(16) float2 g_p1[N_NODES];
__device__ __align__(16) float2 g_p2[N_NODES];
__device__ float g_a3[N_NODES];
// collapsed, PRE-HALVED weight vectors: [P/2 | Q/2 | R/2 | b3/2] (plain stores)
__device__ __align__(16) float g_PQRB[4 * D3];

// ---- grid barrier (count==0 between barriers; gen monotonic) ----
__device__ int g_bar_count;
__device__ volatile int g_bar_gen;

__device__ __forceinline__ void grid_bar() {
    __threadfence();
    __syncthreads();
    if (threadIdx.x == 0) {
        int gen = g_bar_gen;                 // snapshot BEFORE arriving
        if (atomicAdd(&g_bar_count, 1) == GRID - 1) {
            g_bar_count = 0;
            __threadfence();
            g_bar_gen = gen + 1;
        } else {
            while (g_bar_gen == gen) { __nanosleep(40); }
        }
    }
    __syncthreads();
}

__device__ __forceinline__ void red_add_v2(float2* addr, float a, float b) {
    asm volatile("red.global.add.v2.f32 [%0], {%1, %2};"
                 :: "l"(addr), "f"(a), "f"(b) : "memory");
}

__device__ __forceinline__ float fast_tanh(float h) {
    float r;
    asm("tanh.approx.f32 %0, %1;" : "=f"(r) : "f"(h));
    return r;
}

// ---- packed f32x2 helpers (ptxas emits FFMA2 only via PTX fma.rn.f32x2) ----
__device__ __forceinline__ unsigned long long pk2(float lo, float hi) {
    unsigned long long r;
    asm("mov.b64 %0, {%1, %2};" : "=l"(r) : "f"(lo), "f"(hi));
    return r;
}
__device__ __forceinline__ void upk2(float& lo, float& hi, unsigned long long v) {
    asm("mov.b64 {%0, %1}, %2;" : "=f"(lo), "=f"(hi) : "l"(v));
}
__device__ __forceinline__ unsigned long long fma2(unsigned long long a,
                                                   unsigned long long b,
                                                   unsigned long long c) {
    unsigned long long d;
    asm("fma.rn.f32x2 %0, %1, %2, %3;" : "=l"(d) : "l"(a), "l"(b), "l"(c));
    return d;
}

__global__ void __launch_bounds__(TPB, 1)
fused_gcn_kernel(const float* __restrict__ x,
                 const int*   __restrict__ ei,
                 const float* __restrict__ ew,
                 const float* __restrict__ W1,
                 const float* __restrict__ b1,
                 const float* __restrict__ W2,
                 const float* __restrict__ b2,
                 const float* __restrict__ W3,
                 const float* __restrict__ b3,
                 float* __restrict__ out) {
    __shared__ float s_red[1024];
    __shared__ float s_w[D2];       // W12 / bW2 coefficient vector (block-local)

    const int tid  = threadIdx.x;
    const int bid  = blockIdx.x;
    const int gtid = bid * TPB + tid;

    // ---- cache this thread's edges (strided: ALL blocks active) ----
    // e0 = gtid (< GT <= N_EDGES), e1 = gtid + GT for the first 8448 threads.
    const bool has1 = (gtid + GT) < N_EDGES;
    int src0 = ei[gtid];
    int dst0 = ei[N_EDGES + gtid];
    float w0 = ew[gtid];
    int src1 = 0, dst1 = 0; float w1 = 0.f;
    if (has1) {
        src1 = ei[gtid + GT];
        dst1 = ei[N_EDGES + gtid + GT];
        w1   = ew[gtid + GT];
    }

    // ===== P1: edge1 (ALL blocks) || full weight collapse (blocks 144-146) ==
    // (g1,s)[dst] += (w*x[src], w)
    red_add_v2(&g_p1[dst0], w0 * x[src0], w0);
    if (has1) red_add_v2(&g_p1[dst1], w1 * x[src1], w1);

    if (bid >= 144 && bid <= 146) {
        if (bid <= 145) {
            // stage 1: coef[k] = sum_j a[j] * W2[j,k]  (a = W1 or b1)
            const float* a = (bid == 144) ? W1 : b1;
            int k  = tid & 255;
            int jc = tid >> 8;          // 0..3, 32 MACs each
            int j0 = jc * 32;
            float acc = 0.f;
            #pragma unroll 8
            for (int jj = 0; jj < 32; jj++) {
                int j = j0 + jj;
                acc += a[j] * W2[j * D2 + k];
            }
            s_red[jc * 256 + k] = acc;
            __syncthreads();
            if (tid < D2)
                s_w[tid] = s_red[tid] + s_red[256 + tid] + s_red[512 + tid] + s_red[768 + tid];
            __syncthreads();
            // stage 2: vec[m] = sum_k coef[k] * W3[k,m]  -> P (b144) or Q (b145)
            int m = tid & 511;
            int h = tid >> 9;           // 0..1, 128 MACs each
            int k0 = h * 128;
            float acc2 = 0.f;
            #pragma unroll 8
            for (int kk = 0; kk < 128; kk++) {
                int k2 = k0 + kk;
                acc2 += s_w[k2] * W3[k2 * D3 + m];
            }
            s_red[h * 512 + m] = acc2;
            __syncthreads();
            if (tid < D3) {
                int vec = (bid == 144) ? 0 : 1;
                g_PQRB[vec * D3 + tid] = 0.5f * (s_red[tid] + s_red[512 + tid]);
            }
        } else {
            // bid == 146: R[m] = sum_k b2[k]*W3[k,m]; plus b3/2
            int m = tid & 511;
            int h = tid >> 9;
            int k0 = h * 128;
            float acc2 = 0.f;
            #pragma unroll 8
            for (int kk = 0; kk < 128; kk++) {
                int k2 = k0 + kk;
                acc2 += b2[k2] * W3[k2 * D3 + m];
            }
            s_red[h * 512 + m] = acc2;
            __syncthreads();
            if (tid < D3) {
                g_PQRB[2 * D3 + tid] = 0.5f * (s_red[tid] + s_red[512 + tid]);
                g_PQRB[3 * D3 + tid] = 0.5f * b3[tid];
            }
        }
    }

    grid_bar();

    // ===== P2 (pure edges): (a2,t)[dst] += w*(g1,s)[src] ====================
    {
        float2 p = g_p1[src0];
        red_add_v2(&g_p2[dst0], w0 * p.x, w0 * p.y);
        if (has1) {
            float2 q = g_p1[src1];
            red_add_v2(&g_p2[dst1], w1 * q.x, w1 * q.y);
        }
    }

    grid_bar();

    // ===== P3 (pure edges): a3[dst] += w * a2[src] ==========================
    atomicAdd(&g_a3[dst0], w0 * g_p2[src0].x);
    if (has1) atomicAdd(&g_a3[dst1], w1 * g_p2[src1].x);

    grid_bar();

    // ===== P4: out = 0.5*tanh(a3*P' + t*Q' + s*R' + B') + 0.5; then re-zero =
    {
        int j4 = (gtid & 127) << 2;     // loop-invariant feature offset
        float4 P = *reinterpret_cast<const float4*>(&g_PQRB[j4]);
        float4 Q = *reinterpret_cast<const float4*>(&g_PQRB[D3 + j4]);
        float4 R = *reinterpret_cast<const float4*>(&g_PQRB[2 * D3 + j4]);
        float4 B = *reinterpret_cast<const float4*>(&g_PQRB[3 * D3 + j4]);

        unsigned long long P01 = pk2(P.x, P.y), P23 = pk2(P.z, P.w);
        unsigned long long Q01 = pk2(Q.x, Q.y), Q23 = pk2(Q.z, Q.w);
        unsigned long long R01 = pk2(R.x, R.y), R23 = pk2(R.z, R.w);
        unsigned long long B01 = pk2(B.x, B.y), B23 = pk2(B.z, B.w);

        const int n0 = gtid >> 7;

        // depth-1 software pipeline: prefetch next row's 3 scalars while
        // computing the current row (hides the L2 broadcast latency)
        float a3 = g_a3[n0];
        float tt = g_p2[n0].y;
        float ss = g_p1[n0].y;

        for (int n = n0; n < N_NODES; n += ROWSTRIDE) {
            int np = n + ROWSTRIDE;
            float a3n = 0.f, ttn = 0.f, ssn = 0.f;
            if (np < N_NODES) {
                a3n = g_a3[np];
                ttn = g_p2[np].y;
                ssn = g_p1[np].y;
            }

            unsigned long long A2v = pk2(a3, a3);
            unsigned long long T2  = pk2(tt, tt);
            unsigned long long S2  = pk2(ss, ss);

            unsigned long long u01 = fma2(A2v, P01, fma2(T2, Q01, fma2(S2, R01, B01)));
            unsigned long long u23 = fma2(A2v, P23, fma2(T2, Q23, fma2(S2, R23, B23)));

            float4 v;
            upk2(v.x, v.y, u01);
            upk2(v.z, v.w, u23);

            v.x = fmaf(0.5f, fast_tanh(v.x), 0.5f);
            v.y = fmaf(0.5f, fast_tanh(v.y), 0.5f);
            v.z = fmaf(0.5f, fast_tanh(v.z), 0.5f);
            v.w = fmaf(0.5f, fast_tanh(v.w), 0.5f);

            *reinterpret_cast<float4*>(&out[n * D3 + j4]) = v;

            a3 = a3n; tt = ttn; ss = ssn;
        }

        // Tail re-zero: each block zeroes exactly the rows it just read.
        // Row n's 128 readers are 128 contiguous gtids, all inside this block
        // (128 | 1024), so __syncthreads() orders reads before zeroing.
        __syncthreads();
        for (int n = n0; n < N_NODES; n += ROWSTRIDE) {
            if ((tid & 127) == 0) {
                g_p1[n] = make_float2(0.f, 0.f);
                g_p2[n] = make_float2(0.f, 0.f);
                g_a3[n] = 0.f;
            }
        }
    }
}

extern "C" void kernel_launch(void* const* d_in, const int* in_sizes, int n_in,
                              void* d_out, int out_size) {
    const float* x  = (const float*)d_in[0];
    const int*   ei = (const int*)d_in[1];
    const float* ew = (const float*)d_in[2];
    const float* W1 = (const float*)d_in[3];
    const float* b1 = (const float*)d_in[4];
    const float* W2 = (const float*)d_in[5];
    const float* b2 = (const float*)d_in[6];
    const float* W3 = (const float*)d_in[7];
    const float* b3 = (const float*)d_in[8];
    float* out = (float*)d_out;

    fused_gcn_kernel<<<GRID, TPB>>>(x, ei, ew, W1, b1, W2, b2, W3, b3, out);
}

// round 16
// speedup vs baseline: 1.1905x; 1.1905x over previous
#include <cuda_runtime.h>

#define N_NODES 10000
#define N_EDGES 160000
#define D1 128
#define D2 256
#define D3 512

#define GRID 148
#define TPB  1024
#define GT   (GRID * TPB)        // 151552
#define ROWSTRIDE (GT / 128)     // 1184 rows per sweep in phase P4

#define NEB   136                // blocks that own edges
#define ETH   (NEB * TPB)        // 139264 edge-owning threads

// ---- persistent scratch (zero at load; re-zeroed at tail of every run) ----
// pair1[n] = (g1[n], s[n]) ; pair2[n] = (a2[n], t[n])
__device__ __align__(16) float2 g_p1[N_NODES];
__device__ __align__(16) float2 g_p2[N_NODES];
__device__ float g_a3[N_NODES];
__device__ float g_W12[D2];     // W1 @ W2   (plain stores each run)
__device__ float g_bW2[D2];     // b1 @ W2
// collapsed, PRE-HALVED weight vectors: [P/2 | Q/2 | R/2 | b3/2] (plain stores)
__device__ __align__(16) float g_PQRB[4 * D3];

// ---- grid barrier (count==0 between barriers; gen monotonic) ----
__device__ int g_bar_count;
__device__ volatile int g_bar_gen;

__device__ __forceinline__ void grid_bar() {
    __threadfence();
    __syncthreads();
    if (threadIdx.x == 0) {
        int gen = g_bar_gen;                 // snapshot BEFORE arriving
        if (atomicAdd(&g_bar_count, 1) == GRID - 1) {
            g_bar_count = 0;
            __threadfence();
            g_bar_gen = gen + 1;
        } else {
            while (g_bar_gen == gen) { __nanosleep(40); }
        }
    }
    __syncthreads();
}

__device__ __forceinline__ void red_add_v2(float2* addr, float a, float b) {
    asm volatile("red.global.add.v2.f32 [%0], {%1, %2};"
                 :: "l"(addr), "f"(a), "f"(b) : "memory");
}

__device__ __forceinline__ float fast_tanh(float h) {
    float r;
    asm("tanh.approx.f32 %0, %1;" : "=f"(r) : "f"(h));
    return r;
}

// ---- packed f32x2 helpers (ptxas emits FFMA2 only via PTX fma.rn.f32x2) ----
__device__ __forceinline__ unsigned long long pk2(float lo, float hi) {
    unsigned long long r;
    asm("mov.b64 %0, {%1, %2};" : "=l"(r) : "f"(lo), "f"(hi));
    return r;
}
__device__ __forceinline__ void upk2(float& lo, float& hi, unsigned long long v) {
    asm("mov.b64 {%0, %1}, %2;" : "=f"(lo), "=f"(hi) : "l"(v));
}
__device__ __forceinline__ unsigned long long fma2(unsigned long long a,
                                                   unsigned long long b,
                                                   unsigned long long c) {
    unsigned long long d;
    asm("fma.rn.f32x2 %0, %1, %2, %3;" : "=l"(d) : "l"(a), "l"(b), "l"(c));
    return d;
}

__global__ void __launch_bounds__(TPB, 1)
fused_gcn_kernel(const float* __restrict__ x,
                 const int*   __restrict__ ei,
                 const float* __restrict__ ew,
                 const float* __restrict__ W1,
                 const float* __restrict__ b1,
                 const float* __restrict__ W2,
                 const float* __restrict__ b2,
                 const float* __restrict__ W3,
                 const float* __restrict__ b3,
                 float* __restrict__ out) {
    __shared__ float s_red[1024];

    const int tid  = threadIdx.x;
    const int bid  = blockIdx.x;
    const int gtid = bid * TPB + tid;

    // ---- edge ownership: ONLY blocks 0..135 (GEMV blocks own no edges) ----
    // e0 = gtid for gtid < ETH; e1 = gtid + ETH for the first 20736 threads.
    const bool hasE = bid < NEB;
    const bool has1 = hasE && (gtid + ETH) < N_EDGES;
    int src0 = 0, dst0 = 0; float w0 = 0.f;
    int src1 = 0, dst1 = 0; float w1 = 0.f;
    if (hasE) {
        src0 = ei[gtid];
        dst0 = ei[N_EDGES + gtid];
        w0   = ew[gtid];
    }
    if (has1) {
        src1 = ei[gtid + ETH];
        dst1 = ei[N_EDGES + gtid + ETH];
        w1   = ew[gtid + ETH];
    }

    // ===== P1: edges (blocks<136) || W12/bW2 GEMV (144-145, pure) || b3 (146)
    if (hasE) {
        red_add_v2(&g_p1[dst0], w0 * x[src0], w0);
        if (has1) red_add_v2(&g_p1[dst1], w1 * x[src1], w1);
    } else if (bid == 144 || bid == 145) {
        // one PURE block per target vector: 256 cols x 4 j-chunks of 32
        const float* a = (bid == 144) ? W1 : b1;
        int k  = tid & 255;
        int jc = tid >> 8;              // 0..3
        int j0 = jc * 32;
        float acc = 0.f;
        #pragma unroll 8
        for (int jj = 0; jj < 32; jj++) {
            int j = j0 + jj;
            acc += a[j] * W2[j * D2 + k];
        }
        s_red[jc * 256 + k] = acc;
        __syncthreads();
        if (tid < 256) {
            float v = s_red[tid] + s_red[256 + tid] + s_red[512 + tid] + s_red[768 + tid];
            if (bid == 144) g_W12[tid] = v;
            else            g_bW2[tid] = v;
        }
    } else if (bid == 146) {
        if (tid < D3) g_PQRB[3 * D3 + tid] = 0.5f * b3[tid];
    }

    grid_bar();

    // ===== P2: edges (blocks<136) || P/Q/R GEMV (blocks 136-147, pure) ======
    if (hasE) {
        float2 p = g_p1[src0];
        red_add_v2(&g_p2[dst0], w0 * p.x, w0 * p.y);
        if (has1) {
            float2 q = g_p1[src1];
            red_add_v2(&g_p2[dst1], w1 * q.x, w1 * q.y);
        }
    } else {
        // 12 PURE blocks: vec in {P,Q,R} x 4 col-quarters; 8 k-chunks of 32
        int unit = bid - NEB;           // 0..11
        int vec  = unit >> 2;           // 0..2
        int q    = unit & 3;
        int col  = q * 128 + (tid & 127);
        int c    = tid >> 7;            // 0..7
        const float* coef = (vec == 0) ? g_W12 : ((vec == 1) ? g_bW2 : b2);
        int j0 = c * 32;
        float acc = 0.f;
        #pragma unroll 8
        for (int jj = 0; jj < 32; jj++) {
            int j = j0 + jj;
            acc += coef[j] * W3[j * D3 + col];
        }
        s_red[c * 128 + (tid & 127)] = acc;
        __syncthreads();
        if (tid < 128) {
            float v = 0.f;
            #pragma unroll
            for (int c2 = 0; c2 < 8; c2++) v += s_red[c2 * 128 + tid];
            g_PQRB[vec * D3 + q * 128 + tid] = 0.5f * v;
        }
    }

    grid_bar();

    // ===== P3: edges: a3[dst] += w*a2[src]; prefetch first-row (tt,ss) ======
    if (hasE) {
        atomicAdd(&g_a3[dst0], w0 * g_p2[src0].x);
        if (has1) atomicAdd(&g_a3[dst1], w1 * g_p2[src1].x);
    }

    // p1/p2 are FINAL after barrier 2: prefetch row n0's scalars (2 regs)
    const int n0 = gtid >> 7;
    float tt = g_p2[n0].y;
    float ss = g_p1[n0].y;

    grid_bar();

    // ===== P4: out = 0.5*tanh(a3*P' + t*Q' + s*R' + B') + 0.5; then re-zero =
    {
        int j4 = (gtid & 127) << 2;     // loop-invariant feature offset
        float4 P = *reinterpret_cast<const float4*>(&g_PQRB[j4]);
        float4 Q = *reinterpret_cast<const float4*>(&g_PQRB[D3 + j4]);
        float4 R = *reinterpret_cast<const float4*>(&g_PQRB[2 * D3 + j4]);
        float4 B = *reinterpret_cast<const float4*>(&g_PQRB[3 * D3 + j4]);

        unsigned long long P01 = pk2(P.x, P.y), P23 = pk2(P.z, P.w);
        unsigned long long Q01 = pk2(Q.x, Q.y), Q23 = pk2(Q.z, Q.w);
        unsigned long long R01 = pk2(R.x, R.y), R23 = pk2(R.z, R.w);
        unsigned long long B01 = pk2(B.x, B.y), B23 = pk2(B.z, B.w);

        // depth-1 software pipeline: prefetch next row's 3 scalars while
        // computing the current row (hides the L2 broadcast latency)
        float a3 = g_a3[n0];

        for (int n = n0; n < N_NODES; n += ROWSTRIDE) {
            int np = n + ROWSTRIDE;
            float a3n = 0.f, ttn = 0.f, ssn = 0.f;
            if (np < N_NODES) {
                a3n = g_a3[np];
                ttn = g_p2[np].y;
                ssn = g_p1[np].y;
            }

            unsigned long long A2v = pk2(a3, a3);
            unsigned long long T2  = pk2(tt, tt);
            unsigned long long S2  = pk2(ss, ss);

            unsigned long long u01 = fma2(A2v, P01, fma2(T2, Q01, fma2(S2, R01, B01)));
            unsigned long long u23 = fma2(A2v, P23, fma2(T2, Q23, fma2(S2, R23, B23)));

            float4 v;
            upk2(v.x, v.y, u01);
            upk2(v.z, v.w, u23);

            v.x = fmaf(0.5f, fast_tanh(v.x), 0.5f);
            v.y = fmaf(0.5f, fast_tanh(v.y), 0.5f);
            v.z = fmaf(0.5f, fast_tanh(v.z), 0.5f);
            v.w = fmaf(0.5f, fast_tanh(v.w), 0.5f);

            *reinterpret_cast<float4*>(&out[n * D3 + j4]) = v;

            a3 = a3n; tt = ttn; ss = ssn;
        }

        // Tail re-zero: each block zeroes exactly the rows it just read.
        // Row n's 128 readers are 128 contiguous gtids, all inside this block
        // (128 | 1024), so __syncthreads() orders reads before zeroing.
        __syncthreads();
        for (int n = n0; n < N_NODES; n += ROWSTRIDE) {
            if ((tid & 127) == 0) {
                g_p1[n] = make_float2(0.f, 0.f);
                g_p2[n] = make_float2(0.f, 0.f);
                g_a3[n] = 0.f;
            }
        }
    }
}

extern "C" void kernel_launch(void* const* d_in, const int* in_sizes, int n_in,
                              void* d_out, int out_size) {
    const float* x  = (const float*)d_in[0];
    const int*   ei = (const int*)d_in[1];
    const float* ew = (const float*)d_in[2];
    const float* W1 = (const float*)d_in[3];
    const float* b1 = (const float*)d_in[4];
    const float* W2 = (const float*)d_in[5];
    const float* b2 = (const float*)d_in[6];
    const float* W3 = (const float*)d_in[7];
    const float* b3 = (const float*)d_in[8];
    float* out = (float*)d_out;

    fused_gcn_kernel<<<GRID, TPB>>>(x, ei, ew, W1, b1, W2, b2, W3, b3, out);
}

// round 17
// speedup vs baseline: 1.1922x; 1.0014x over previous
#include <cuda_runtime.h>

#define N_NODES 10000
#define N_EDGES 160000
#define D1 128
#define D2 256
#define D3 512

#define GRID 296
#define TPB  512
#define GT   (GRID * TPB)        // 151552
#define ROWSTRIDE (GT / 128)     // 1184 rows per sweep in phase P4

#define NEB   280                // blocks that own edges
#define ETH   (NEB * TPB)        // 143360 edge-owning threads (rest: 16640 2nd edges)

// ---- persistent scratch (zero at load; re-zeroed at tail of every run) ----
// pair1[n] = (g1[n], s[n]) ; pair2[n] = (a2[n], t[n])
__device__ __align__(16) float2 g_p1[N_NODES];
__device__ __align__(16) float2 g_p2[N_NODES];
__device__ float g_a3[N_NODES];
__device__ float g_W12[D2];     // W1 @ W2   (plain stores each run)
__device__ float g_bW2[D2];     // b1 @ W2
// collapsed, PRE-HALVED weight vectors: [P/2 | Q/2 | R/2 | b3/2] (plain stores)
__device__ __align__(16) float g_PQRB[4 * D3];

// ---- grid barrier (count==0 between barriers; gen monotonic) ----
__device__ int g_bar_count;
__device__ volatile int g_bar_gen;

__device__ __forceinline__ void grid_bar() {
    __threadfence();
    __syncthreads();
    if (threadIdx.x == 0) {
        int gen = g_bar_gen;                 // snapshot BEFORE arriving
        if (atomicAdd(&g_bar_count, 1) == GRID - 1) {
            g_bar_count = 0;
            __threadfence();
            g_bar_gen = gen + 1;
        } else {
            while (g_bar_gen == gen) { __nanosleep(40); }
        }
    }
    __syncthreads();
}

__device__ __forceinline__ void red_add_v2(float2* addr, float a, float b) {
    asm volatile("red.global.add.v2.f32 [%0], {%1, %2};"
                 :: "l"(addr), "f"(a), "f"(b) : "memory");
}

__device__ __forceinline__ float fast_tanh(float h) {
    float r;
    asm("tanh.approx.f32 %0, %1;" : "=f"(r) : "f"(h));
    return r;
}

// ---- packed f32x2 helpers (ptxas emits FFMA2 only via PTX fma.rn.f32x2) ----
__device__ __forceinline__ unsigned long long pk2(float lo, float hi) {
    unsigned long long r;
    asm("mov.b64 %0, {%1, %2};" : "=l"(r) : "f"(lo), "f"(hi));
    return r;
}
__device__ __forceinline__ void upk2(float& lo, float& hi, unsigned long long v) {
    asm("mov.b64 {%0, %1}, %2;" : "=f"(lo), "=f"(hi) : "l"(v));
}
__device__ __forceinline__ unsigned long long fma2(unsigned long long a,
                                                   unsigned long long b,
                                                   unsigned long long c) {
    unsigned long long d;
    asm("fma.rn.f32x2 %0, %1, %2, %3;" : "=l"(d) : "l"(a), "l"(b), "l"(c));
    return d;
}

__global__ void __launch_bounds__(TPB, 2)
fused_gcn_kernel(const float* __restrict__ x,
                 const int*   __restrict__ ei,
                 const float* __restrict__ ew,
                 const float* __restrict__ W1,
                 const float* __restrict__ b1,
                 const float* __restrict__ W2,
                 const float* __restrict__ b2,
                 const float* __restrict__ W3,
                 const float* __restrict__ b3,
                 float* __restrict__ out) {
    __shared__ float s_red[512];

    const int tid  = threadIdx.x;
    const int bid  = blockIdx.x;
    const int gtid = bid * TPB + tid;

    // ---- edge ownership: ONLY blocks 0..279 (GEMV blocks own no edges) ----
    // e0 = gtid for gtid < ETH; e1 = gtid + ETH for the first 16640 threads.
    const bool hasE = bid < NEB;
    const bool has1 = hasE && (gtid + ETH) < N_EDGES;
    int src0 = 0, dst0 = 0; float w0 = 0.f;
    int src1 = 0, dst1 = 0; float w1 = 0.f;
    if (hasE) {
        src0 = ei[gtid];
        dst0 = ei[N_EDGES + gtid];
        w0   = ew[gtid];
    }
    if (has1) {
        src1 = ei[gtid + ETH];
        dst1 = ei[N_EDGES + gtid + ETH];
        w1   = ew[gtid + ETH];
    }

    // ===== P1: edges (blocks<280) || W12/bW2 GEMV (280-281, pure) || b3 (282)
    if (hasE) {
        red_add_v2(&g_p1[dst0], w0 * x[src0], w0);
        if (has1) red_add_v2(&g_p1[dst1], w1 * x[src1], w1);
    } else if (bid == 280 || bid == 281) {
        // one PURE block per target vector: 256 cols x 2 j-chunks of 64
        const float* a = (bid == 280) ? W1 : b1;
        int k  = tid & 255;
        int jc = tid >> 8;              // 0..1
        int j0 = jc * 64;
        float acc = 0.f;
        #pragma unroll 8
        for (int jj = 0; jj < 64; jj++) {
            int j = j0 + jj;
            acc += a[j] * W2[j * D2 + k];
        }
        s_red[jc * 256 + k] = acc;
        __syncthreads();
        if (tid < 256) {
            float v = s_red[tid] + s_red[256 + tid];
            if (bid == 280) g_W12[tid] = v;
            else            g_bW2[tid] = v;
        }
    } else if (bid == 282) {
        g_PQRB[3 * D3 + tid] = 0.5f * b3[tid];   // tid < 512 = D3
    }

    grid_bar();

    // ===== P2: edges (blocks<280) || P/Q/R GEMV (blocks 284-295, pure) ======
    if (hasE) {
        float2 p = g_p1[src0];
        red_add_v2(&g_p2[dst0], w0 * p.x, w0 * p.y);
        if (has1) {
            float2 q = g_p1[src1];
            red_add_v2(&g_p2[dst1], w1 * q.x, w1 * q.y);
        }
    } else if (bid >= 284) {
        // 12 PURE blocks: vec in {P,Q,R} x 4 col-quarters; 4 k-chunks of 64
        int unit = bid - 284;           // 0..11
        int vec  = unit >> 2;           // 0..2
        int q    = unit & 3;
        int col  = q * 128 + (tid & 127);
        int c    = tid >> 7;            // 0..3
        const float* coef = (vec == 0) ? g_W12 : ((vec == 1) ? g_bW2 : b2);
        int j0 = c * 64;
        float acc = 0.f;
        #pragma unroll 8
        for (int jj = 0; jj < 64; jj++) {
            int j = j0 + jj;
            acc += coef[j] * W3[j * D3 + col];
        }
        s_red[c * 128 + (tid & 127)] = acc;
        __syncthreads();
        if (tid < 128) {
            float v = s_red[tid] + s_red[128 + tid] + s_red[256 + tid] + s_red[384 + tid];
            g_PQRB[vec * D3 + q * 128 + tid] = 0.5f * v;
        }
    }

    grid_bar();

    // ===== P3: edges: a3[dst] += w*a2[src]; prefetch first-row (tt,ss) ======
    if (hasE) {
        atomicAdd(&g_a3[dst0], w0 * g_p2[src0].x);
        if (has1) atomicAdd(&g_a3[dst1], w1 * g_p2[src1].x);
    }

    // p1/p2 are FINAL after barrier 2: prefetch row n0's scalars (2 regs)
    const int n0 = gtid >> 7;
    float tt = g_p2[n0].y;
    float ss = g_p1[n0].y;

    grid_bar();

    // ===== P4: out = 0.5*tanh(a3*P' + t*Q' + s*R' + B') + 0.5; then re-zero =
    {
        int j4 = (gtid & 127) << 2;     // loop-invariant feature offset
        float4 P = *reinterpret_cast<const float4*>(&g_PQRB[j4]);
        float4 Q = *reinterpret_cast<const float4*>(&g_PQRB[D3 + j4]);
        float4 R = *reinterpret_cast<const float4*>(&g_PQRB[2 * D3 + j4]);
        float4 B = *reinterpret_cast<const float4*>(&g_PQRB[3 * D3 + j4]);

        unsigned long long P01 = pk2(P.x, P.y), P23 = pk2(P.z, P.w);
        unsigned long long Q01 = pk2(Q.x, Q.y), Q23 = pk2(Q.z, Q.w);
        unsigned long long R01 = pk2(R.x, R.y), R23 = pk2(R.z, R.w);
        unsigned long long B01 = pk2(B.x, B.y), B23 = pk2(B.z, B.w);

        // depth-1 software pipeline: prefetch next row's 3 scalars while
        // computing the current row (hides the L2 broadcast latency)
        float a3 = g_a3[n0];

        for (int n = n0; n < N_NODES; n += ROWSTRIDE) {
            int np = n + ROWSTRIDE;
            float a3n = 0.f, ttn = 0.f, ssn = 0.f;
            if (np < N_NODES) {
                a3n = g_a3[np];
                ttn = g_p2[np].y;
                ssn = g_p1[np].y;
            }

            unsigned long long A2v = pk2(a3, a3);
            unsigned long long T2  = pk2(tt, tt);
            unsigned long long S2  = pk2(ss, ss);

            unsigned long long u01 = fma2(A2v, P01, fma2(T2, Q01, fma2(S2, R01, B01)));
            unsigned long long u23 = fma2(A2v, P23, fma2(T2, Q23, fma2(S2, R23, B23)));

            float4 v;
            upk2(v.x, v.y, u01);
            upk2(v.z, v.w, u23);

            v.x = fmaf(0.5f, fast_tanh(v.x), 0.5f);
            v.y = fmaf(0.5f, fast_tanh(v.y), 0.5f);
            v.z = fmaf(0.5f, fast_tanh(v.z), 0.5f);
            v.w = fmaf(0.5f, fast_tanh(v.w), 0.5f);

            *reinterpret_cast<float4*>(&out[n * D3 + j4]) = v;

            a3 = a3n; tt = ttn; ss = ssn;
        }

        // Tail re-zero: each block zeroes exactly the rows it just read.
        // Row n's 128 readers are 128 contiguous gtids, all inside this block
        // (128 | 512), so __syncthreads() orders reads before zeroing.
        __syncthreads();
        for (int n = n0; n < N_NODES; n += ROWSTRIDE) {
            if ((tid & 127) == 0) {
                g_p1[n] = make_float2(0.f, 0.f);
                g_p2[n] = make_float2(0.f, 0.f);
                g_a3[n] = 0.f;
            }
        }
    }
}

extern "C" void kernel_launch(void* const* d_in, const int* in_sizes, int n_in,
                              void* d_out, int out_size) {
    const float* x  = (const float*)d_in[0];
    const int*   ei = (const int*)d_in[1];
    const float* ew = (const float*)d_in[2];
    const float* W1 = (const float*)d_in[3];
    const float* b1 = (const float*)d_in[4];
    const float* W2 = (const float*)d_in[5];
    const float* b2 = (const float*)d_in[6];
    const float* W3 = (const float*)d_in[7];
    const float* b3 = (const float*)d_in[8];
    float* out = (float*)d_out;

    fused_gcn_kernel<<<GRID, TPB>>>(x, ei, ew, W1, b1, W2, b2, W3, b3, out);
}